// round 5
// baseline (speedup 1.0000x reference)
#include <cuda_runtime.h>
#include <cstdint>

#define NT 256
#define ROWP 130

typedef unsigned long long u64;

// Pool offsets (floats), pitch 130: 64-feature buffer = 8320 floats
#define OFF_U    0        // 128 x 130 = 16640   (A,B)    -> GB part1
#define OFF_H1   16640    // 64 x 130  = 8320    (B; SIG in D) -> GB part2
#define OFF_MN   24960    // 64 x 130  = 8320    (B..D; RES in D..E, in-place)
#define OFF_WD   33280    // 8192 duplicated-weight staging (K<=64)
#define OFF_HT   41472    // 64 x 130  = 8320    (persistent raw ht)
#define OFF_GB   0        // 192 x 130 = 24960   (E, aliases U+H1)
#define SMEM_FLOATS 49792 // 199168 bytes dynamic

__device__ float g_adj[2048];

static __device__ __forceinline__ float clipf(float x, float lo, float hi) {
    return fminf(fmaxf(x, lo), hi);
}
static __device__ __forceinline__ float sigf(float x) {
    return 1.0f / (1.0f + expf(-x));
}
static __device__ __forceinline__ u64 ffma2(u64 a, u64 b, u64 c) {
    u64 d;
    asm("fma.rn.f32x2 %0, %1, %2, %3;" : "=l"(d) : "l"(a), "l"(b), "l"(c));
    return d;
}
static __device__ __forceinline__ float2 u2f(u64 v) {
    float2 f;
    f.x = __uint_as_float((unsigned)v);
    f.y = __uint_as_float((unsigned)(v >> 32));
    return f;
}

// ---------------------------------------------------------------------------
// adj[k][d] = clip( sum_c a0[c]*graphs[k,c,d] / max(sum(a0),1), -5, 5 )
// ---------------------------------------------------------------------------
__global__ void adj_kernel(const int* __restrict__ qt,
                           const float* __restrict__ one_hot,
                           const float* __restrict__ graphs)
{
    __shared__ int nzIdx[1024];
    __shared__ int nzCnt;
    const int k = blockIdx.x;
    const int tid = threadIdx.x;
    if (tid == 0) nzCnt = 0;
    __syncthreads();
    const int q0 = __ldg(&qt[0]);
    const float v = __ldg(&one_hot[(size_t)q0 * 1024 + tid]);
    if (v > 0.5f) { int p = atomicAdd(&nzCnt, 1); nzIdx[p] = tid; }
    __syncthreads();
    const int cnt = nzCnt;
    const float denom = fmaxf((float)cnt, 1.0f);
    float s = 0.0f;
    for (int t = 0; t < cnt; ++t)
        s += __ldg(&graphs[((size_t)k * 1024 + (size_t)nzIdx[t]) * 1024 + tid]);
    g_adj[k * 1024 + tid] = clipf(s / denom, -5.0f, 5.0f);
}

// ---------------------------------------------------------------------------
// Packed-f32x2 GEMM tile: M=128 rows (pairs), N=64 cols, K given.
// A: [k][ROWP] shared (row fastest). Wd: [k][128] duplicated pairs.
// Thread (tx 0..15, ty 0..15): rows ty*8..+7 (4 pairs), cols j = tx + 16*cc.
// acc accumulates (caller zeros).
// ---------------------------------------------------------------------------
static __device__ __forceinline__ void gemm2(const float* __restrict__ A,
                                             const float* __restrict__ Wd,
                                             int K, int tx, int ty,
                                             u64 acc[4][4])
{
    const float* Ap = A + ty * 8;
    const float* Wp = Wd + 2 * tx;
#pragma unroll 4
    for (int k = 0; k < K; ++k) {
        u64 a[4], w[4];
#pragma unroll
        for (int r = 0; r < 4; ++r)
            a[r] = *reinterpret_cast<const u64*>(Ap + (size_t)k * ROWP + 2 * r);
#pragma unroll
        for (int c = 0; c < 4; ++c)
            w[c] = *reinterpret_cast<const u64*>(Wp + (size_t)k * 128 + 32 * c);
#pragma unroll
        for (int r = 0; r < 4; ++r)
#pragma unroll
            for (int c = 0; c < 4; ++c)
                acc[r][c] = ffma2(a[r], w[c], acc[r][c]);
    }
}

static __device__ __forceinline__ void zero_acc(u64 acc[4][4]) {
#pragma unroll
    for (int r = 0; r < 4; ++r)
#pragma unroll
        for (int c = 0; c < 4; ++c) acc[r][c] = 0ull;
}

// Stage K x 64 row-major weights into duplicated layout Wd[k][128].
static __device__ __forceinline__ void stage_dup(const float* __restrict__ g,
                                                 float* __restrict__ s,
                                                 int Kk, int tid)
{
    const int n = Kk * 16;
    for (int i = tid; i < n; i += NT) {
        const float4 v = __ldg(reinterpret_cast<const float4*>(g) + i);
        const int k = i >> 4, j4 = i & 15;
        reinterpret_cast<float4*>(s)[k * 32 + j4 * 2]     = make_float4(v.x, v.x, v.y, v.y);
        reinterpret_cast<float4*>(s)[k * 32 + j4 * 2 + 1] = make_float4(v.z, v.z, v.w, v.w);
    }
}

// Stage 64-col slice [j0, j0+64) of a (64 x 192) row-major matrix, duplicated.
static __device__ __forceinline__ void stage_dup_slice192(const float* __restrict__ g,
                                                          int j0, float* __restrict__ s,
                                                          int tid)
{
    for (int i = tid; i < 64 * 16; i += NT) {
        const int k = i >> 4, j4 = i & 15;
        const float4 v = __ldg(reinterpret_cast<const float4*>(&g[k * 192 + j0]) + j4);
        reinterpret_cast<float4*>(s)[k * 32 + j4 * 2]     = make_float4(v.x, v.x, v.y, v.y);
        reinterpret_cast<float4*>(s)[k * 32 + j4 * 2 + 1] = make_float4(v.z, v.z, v.w, v.w);
    }
}

// ---------------------------------------------------------------------------
// Main fused kernel: one block per (b, 128-row c-tile).
// ---------------------------------------------------------------------------
extern __shared__ float dynsmem[];

__global__ void __launch_bounds__(NT, 1)
main_kernel(const int*   __restrict__ qt,
            const float* __restrict__ ht,
            const float* __restrict__ one_hot,
            const float* __restrict__ kcE,
            const float* __restrict__ nwp,
            const float* __restrict__ Ws1, const float* __restrict__ bs1,
            const float* __restrict__ Ws2, const float* __restrict__ bs2,
            const float* __restrict__ Wn1, const float* __restrict__ bn1,
            const float* __restrict__ Wn2, const float* __restrict__ bn2,
            const float* __restrict__ ea_w,
            const float* __restrict__ We,  const float* __restrict__ be,
            const float* __restrict__ Wa,  const float* __restrict__ ba,
            const float* __restrict__ W_ih, const float* __restrict__ b_ih,
            const float* __restrict__ W_hh, const float* __restrict__ b_hh,
            const float* __restrict__ Wpv, const float* __restrict__ bp,
            float* __restrict__ out)
{
    const int tid = threadIdx.x;
    const int tx = tid & 15;
    const int ty = tid >> 4;
    const int c0 = blockIdx.x * 128;
    const int b  = blockIdx.y;

    float* pool = dynsmem;
    float* U   = pool + OFF_U;
    float* H1  = pool + OFF_H1;    // also SIG
    float* MN  = pool + OFF_MN;    // also RES (in place)
    float* Wd  = pool + OFF_WD;
    float* HT  = pool + OFF_HT;
    float* GB  = pool + OFF_GB;

    __shared__ float adj0S[128], adj1S[128], eaS[128], yS[128], WpS[64];
    __shared__ float selfH1[8][64];
    __shared__ int selfRows[128];
    __shared__ int selfCnt;

    if (tid == 0) selfCnt = 0;
    __syncthreads();

    // ---------------- Phase A: metadata + build HT / U ------------------------
    const int qb = __ldg(&qt[b]);
    if (tid < 128) {
        const int row = tid;
        const int c = c0 + row;
        const float m = __ldg(&one_hot[(size_t)qb * 1024 + c]);
        adj0S[row] = g_adj[c];
        adj1S[row] = g_adj[1024 + c];
        eaS[row]   = __ldg(&ea_w[c]);
        if (m > 0.5f) { int p = atomicAdd(&selfCnt, 1); selfRows[p] = row; }
    }
    if (tid < 64) WpS[tid] = __ldg(&Wpv[tid]);

    // row-fastest mapping: conflict-free transposed smem stores
    for (int i = tid; i < 2048; i += NT) {
        const int row = i & 127;
        const int f4  = i >> 7;
        const float4 v = __ldg(reinterpret_cast<const float4*>(
                               &ht[((size_t)b * 1024 + c0 + row) * 64]) + f4);
        const int f = f4 * 4;
        HT[(f + 0) * ROWP + row] = v.x;
        HT[(f + 1) * ROWP + row] = v.y;
        HT[(f + 2) * ROWP + row] = v.z;
        HT[(f + 3) * ROWP + row] = v.w;
        U[(f + 0) * ROWP + row] = clipf(v.x, -5.0f, 5.0f);
        U[(f + 1) * ROWP + row] = clipf(v.y, -5.0f, 5.0f);
        U[(f + 2) * ROWP + row] = clipf(v.z, -5.0f, 5.0f);
        U[(f + 3) * ROWP + row] = clipf(v.w, -5.0f, 5.0f);
    }
    for (int i = tid; i < 2048; i += NT) {
        const int row = i & 127;
        const int f4  = i >> 7;
        const float4 v = __ldg(reinterpret_cast<const float4*>(
                               &kcE[(size_t)(c0 + row) * 64]) + f4);
        const int f = 64 + f4 * 4;
        U[(f + 0) * ROWP + row] = clipf(v.x, -5.0f, 5.0f);
        U[(f + 1) * ROWP + row] = clipf(v.y, -5.0f, 5.0f);
        U[(f + 2) * ROWP + row] = clipf(v.z, -5.0f, 5.0f);
        U[(f + 3) * ROWP + row] = clipf(v.w, -5.0f, 5.0f);
    }
    __syncthreads();

    const float w = clipf(__ldg(&nwp[0]), 0.1f, 0.9f);
    u64 acc[4][4];

    // ---------------- Phase B: neighbor MLPs (valid for mask==0 rows) ---------
    // neigh_ht = [0, clip(t)] => only Wn1[k][128:256] contributes. K=128 split 2x64.
#pragma unroll 1
    for (int k = 0; k < 2; ++k) {
        zero_acc(acc);
#pragma unroll 1
        for (int half = 0; half < 2; ++half) {
            stage_dup(Wn1 + (size_t)k * 16384 + 8192 + half * 4096, Wd, 64, tid);
            __syncthreads();
            gemm2(U + half * 64 * ROWP, Wd, 64, tx, ty, acc);
            __syncthreads();
        }
        const float* bn1k = bn1 + k * 64;
#pragma unroll
        for (int cc = 0; cc < 4; ++cc) {
            const int j = tx + 16 * cc;
            const float bb = __ldg(&bn1k[j]);
#pragma unroll
            for (int r = 0; r < 4; ++r) {
                const float2 v = u2f(acc[r][cc]);
                *reinterpret_cast<float2*>(&H1[(size_t)j * ROWP + ty * 8 + 2 * r]) =
                    make_float2(fmaxf(v.x + bb, 0.0f), fmaxf(v.y + bb, 0.0f));
            }
        }
        __syncthreads();

        stage_dup(Wn2 + (size_t)k * 4096, Wd, 64, tid);
        __syncthreads();
        zero_acc(acc);
        gemm2(H1, Wd, 64, tx, ty, acc);
        const float* bn2k = bn2 + k * 64;
#pragma unroll
        for (int cc = 0; cc < 4; ++cc) {
            const int j = tx + 16 * cc;
            const float bb = __ldg(&bn2k[j]);
#pragma unroll
            for (int r = 0; r < 4; ++r) {
                const int row2 = ty * 8 + 2 * r;
                const float2 v = u2f(acc[r][cc]);
                const float nb0 = fminf(fmaxf(v.x + bb, 0.0f), 5.0f);
                const float nb1 = fminf(fmaxf(v.y + bb, 0.0f), 5.0f);
                float2* mp = reinterpret_cast<float2*>(&MN[(size_t)j * ROWP + row2]);
                if (k == 0) {
                    *mp = make_float2(clipf(adj0S[row2] * nb0, -5.0f, 5.0f),
                                      clipf(adj0S[row2 + 1] * nb1, -5.0f, 5.0f));
                } else {
                    const float2 old = *mp;
                    *mp = make_float2(
                        clipf(w * old.x + (1.0f - w) * adj1S[row2] * nb0, -5.0f, 5.0f),
                        clipf(w * old.y + (1.0f - w) * adj1S[row2 + 1] * nb1, -5.0f, 5.0f));
                }
            }
        }
        __syncthreads();
    }

    // ---------------- Phase C: sparse self-MLP fixup (mask==1 rows) -----------
    {
        const int nSelf = selfCnt;
        const int warpId = tid >> 5;
        const int lane = tid & 31;
        for (int s = warpId; s < nSelf; s += 8) {
            const int row = selfRows[s];
            const int c = c0 + row;
            float a1 = __ldg(&bs1[lane]);
            float a2 = __ldg(&bs1[lane + 32]);
#pragma unroll 4
            for (int i = 0; i < 64; ++i) {
                const float xi = HT[i * ROWP + row];
                a1 = fmaf(xi, __ldg(&Ws1[i * 64 + lane]), a1);
                a2 = fmaf(xi, __ldg(&Ws1[i * 64 + lane + 32]), a2);
            }
#pragma unroll 4
            for (int i = 0; i < 64; ++i) {
                const float xi = __ldg(&kcE[(size_t)c * 64 + i]);
                a1 = fmaf(xi, __ldg(&Ws1[(64 + i) * 64 + lane]), a1);
                a2 = fmaf(xi, __ldg(&Ws1[(64 + i) * 64 + lane + 32]), a2);
            }
            selfH1[warpId][lane]      = fmaxf(a1, 0.0f);
            selfH1[warpId][lane + 32] = fmaxf(a2, 0.0f);
            __syncwarp();
            float o1 = __ldg(&bs2[lane]);
            float o2 = __ldg(&bs2[lane + 32]);
#pragma unroll 4
            for (int i = 0; i < 64; ++i) {
                const float h = selfH1[warpId][i];
                o1 = fmaf(h, __ldg(&Ws2[i * 64 + lane]), o1);
                o2 = fmaf(h, __ldg(&Ws2[i * 64 + lane + 32]), o2);
            }
            MN[(size_t)lane * ROWP + row]        = fminf(fmaxf(o1, 0.0f), 10.0f);
            MN[(size_t)(lane + 32) * ROWP + row] = fminf(fmaxf(o2, 0.0f), 10.0f);
            __syncwarp();
        }
    }
    __syncthreads();

    // ---------------- Phase D: edge-attention residual (RES in place of MN) ---
    float* SIG = H1;
    float* RES = MN;

    stage_dup(We, Wd, 64, tid);
    __syncthreads();
    zero_acc(acc);
    gemm2(MN, Wd, 64, tx, ty, acc);
#pragma unroll
    for (int cc = 0; cc < 4; ++cc) {
        const int j = tx + 16 * cc;
        const float bb = __ldg(&be[j]);
#pragma unroll
        for (int r = 0; r < 4; ++r) {
            const float2 v = u2f(acc[r][cc]);
            *reinterpret_cast<float2*>(&SIG[(size_t)j * ROWP + ty * 8 + 2 * r]) =
                make_float2(sigf(v.x + bb), sigf(v.y + bb));
        }
    }
    __syncthreads();

    stage_dup(Wa, Wd, 64, tid);
    __syncthreads();
    zero_acc(acc);
    gemm2(MN, Wd, 64, tx, ty, acc);
    __syncthreads();   // all reads of MN complete before in-place RES writes
#pragma unroll
    for (int cc = 0; cc < 4; ++cc) {
        const int j = tx + 16 * cc;
        const float bb = __ldg(&ba[j]);
#pragma unroll
        for (int r = 0; r < 4; ++r) {
            const int row2 = ty * 8 + 2 * r;
            const float2 v = u2f(acc[r][cc]);
            const float2 mn = *reinterpret_cast<const float2*>(&MN[(size_t)j * ROWP + row2]);
            const float2 sg = *reinterpret_cast<const float2*>(&SIG[(size_t)j * ROWP + row2]);
            const float g0 = eaS[row2], g1 = eaS[row2 + 1];
            *reinterpret_cast<float2*>(&RES[(size_t)j * ROWP + row2]) = make_float2(
                mn.x - g0 * sg.x * mn.x + g0 * tanhf(v.x + bb),
                mn.y - g1 * sg.y * mn.y + g1 * tanhf(v.y + bb));
        }
    }
    __syncthreads();

    // ---------------- Phase E: GRU + readout ----------------------------------
    // gh = ht @ W_hh + b_hh  (3 passes of 64 cols into GB)
#pragma unroll 1
    for (int p = 0; p < 3; ++p) {
        stage_dup_slice192(W_hh, p * 64, Wd, tid);
        __syncthreads();
        zero_acc(acc);
        gemm2(HT, Wd, 64, tx, ty, acc);
#pragma unroll
        for (int cc = 0; cc < 4; ++cc) {
            const int j = p * 64 + tx + 16 * cc;
            const float bb = __ldg(&b_hh[j]);
#pragma unroll
            for (int r = 0; r < 4; ++r) {
                const float2 v = u2f(acc[r][cc]);
                *reinterpret_cast<float2*>(&GB[(size_t)j * ROWP + ty * 8 + 2 * r]) =
                    make_float2(v.x + bb, v.y + bb);
            }
        }
        __syncthreads();
    }

    // gi passes 0,1: r = sigmoid(ir+hr), z = sigmoid(iz+hz), fused in place
#pragma unroll 1
    for (int p = 0; p < 2; ++p) {
        stage_dup_slice192(W_ih, p * 64, Wd, tid);
        __syncthreads();
        zero_acc(acc);
        gemm2(RES, Wd, 64, tx, ty, acc);
#pragma unroll
        for (int cc = 0; cc < 4; ++cc) {
            const int j = p * 64 + tx + 16 * cc;
            const float bb = __ldg(&b_ih[j]);
#pragma unroll
            for (int r = 0; r < 4; ++r) {
                const float2 v = u2f(acc[r][cc]);
                float2* gp = reinterpret_cast<float2*>(&GB[(size_t)j * ROWP + ty * 8 + 2 * r]);
                const float2 old = *gp;
                *gp = make_float2(sigf(v.x + bb + old.x), sigf(v.y + bb + old.y));
            }
        }
        __syncthreads();
    }

    // gi pass 2: n = tanh(in + r*hn); h_next = (1-z)*n + z*ht; y = h_next . Wp
    stage_dup_slice192(W_ih, 128, Wd, tid);
    __syncthreads();
    zero_acc(acc);
    gemm2(RES, Wd, 64, tx, ty, acc);
    {
        float yp[8];
#pragma unroll
        for (int q = 0; q < 8; ++q) yp[q] = 0.0f;
#pragma unroll
        for (int cc = 0; cc < 4; ++cc) {
            const int f = tx + 16 * cc;
            const float bb = __ldg(&b_ih[128 + f]);
            const float wp = WpS[f];
#pragma unroll
            for (int r = 0; r < 4; ++r) {
                const int row2 = ty * 8 + 2 * r;
                const float2 v  = u2f(acc[r][cc]);
                const float2 rg = *reinterpret_cast<const float2*>(&GB[(size_t)f * ROWP + row2]);
                const float2 zg = *reinterpret_cast<const float2*>(&GB[(size_t)(64 + f) * ROWP + row2]);
                const float2 hn = *reinterpret_cast<const float2*>(&GB[(size_t)(128 + f) * ROWP + row2]);
                const float2 hv = *reinterpret_cast<const float2*>(&HT[(size_t)f * ROWP + row2]);
                const float n0 = tanhf(v.x + bb + rg.x * hn.x);
                const float n1 = tanhf(v.y + bb + rg.y * hn.y);
                const float h0 = (1.0f - zg.x) * n0 + zg.x * hv.x;
                const float h1 = (1.0f - zg.y) * n1 + zg.y * hv.y;
                yp[2 * r]     += h0 * wp;
                yp[2 * r + 1] += h1 * wp;
            }
        }
#pragma unroll
        for (int q = 0; q < 8; ++q) {
            float s = yp[q];
#pragma unroll
            for (int off = 1; off < 16; off <<= 1)
                s += __shfl_xor_sync(0xffffffffu, s, off);
            if (tx == 0) yS[ty * 8 + q] = s;
        }
    }
    __syncthreads();

    if (tid < 128) {
        out[(size_t)b * 1024 + c0 + tid] = sigf(yS[tid] + __ldg(&bp[0]));
    }
}

// ---------------------------------------------------------------------------
// Launcher
// ---------------------------------------------------------------------------
extern "C" void kernel_launch(void* const* d_in, const int* in_sizes, int n_in,
                              void* d_out, int out_size)
{
    const int*   qt     = (const int*)  d_in[1];
    const float* ht     = (const float*)d_in[2];
    const float* oh     = (const float*)d_in[3];
    const float* kcE    = (const float*)d_in[4];
    const float* graphs = (const float*)d_in[5];
    const float* nw     = (const float*)d_in[6];
    const float* Ws1    = (const float*)d_in[7];
    const float* bs1    = (const float*)d_in[8];
    const float* Ws2    = (const float*)d_in[9];
    const float* bs2    = (const float*)d_in[10];
    const float* Wn1    = (const float*)d_in[11];
    const float* bn1    = (const float*)d_in[12];
    const float* Wn2    = (const float*)d_in[13];
    const float* bn2    = (const float*)d_in[14];
    const float* ea     = (const float*)d_in[15];
    const float* We     = (const float*)d_in[16];
    const float* be     = (const float*)d_in[17];
    const float* Wa     = (const float*)d_in[18];
    const float* ba     = (const float*)d_in[19];
    const float* Wih    = (const float*)d_in[20];
    const float* bih    = (const float*)d_in[21];
    const float* Whh    = (const float*)d_in[22];
    const float* bhh    = (const float*)d_in[23];
    const float* Wp     = (const float*)d_in[24];
    const float* bp     = (const float*)d_in[25];
    float* out = (float*)d_out;

    adj_kernel<<<2, 1024>>>(qt, oh, graphs);

    const int smemBytes = SMEM_FLOATS * (int)sizeof(float); // 199168
    cudaFuncSetAttribute(main_kernel,
                         cudaFuncAttributeMaxDynamicSharedMemorySize, smemBytes);

    dim3 grid(8, 256);
    main_kernel<<<grid, NT, smemBytes>>>(qt, ht, oh, kcE, nw,
                                         Ws1, bs1, Ws2, bs2,
                                         Wn1, bn1, Wn2, bn2,
                                         ea, We, be, Wa, ba,
                                         Wih, bih, Whh, bhh, Wp, bp, out);
}

// round 6
// speedup vs baseline: 1.4415x; 1.4415x over previous
#include <cuda_runtime.h>
#include <cstdint>

#define NT 512
#define ROWP 129

// Pool offsets (floats)
#define OFF_GB   0        // 192 x 129 = 24768 (phase E; cols 0..63 alias U, 64..127 alias H1)
#define OFF_U    0        // 64 x 129 = 8256  (clip(ht), phase B)
#define OFF_H1   8256     // 64 x 129 = 8256  (B hidden; SIG in D)
#define OFF_MN   24768    // 64 x 129 = 8256  (B..D; RES D..E in place)
#define OFF_HT   33024    // 64 x 129 = 8256  (raw ht, persistent)
#define OFF_WF   41280    // 4096 frag-order weight staging (K=64 x N=64)
#define SMEM_FLOATS 45376 // 181504 bytes

__device__ float g_adj[2048];
__device__ float g_P1[2 * 1024 * 64];   // kc-precomputed layer-1 bias plane

static __device__ __forceinline__ float clipf(float x, float lo, float hi) {
    return fminf(fmaxf(x, lo), hi);
}
static __device__ __forceinline__ float sigf(float x) {
    return 1.0f / (1.0f + expf(-x));
}
static __device__ __forceinline__ unsigned f2tf(float x) {
    unsigned r;
    asm("cvt.rna.tf32.f32 %0, %1;" : "=r"(r) : "f"(x));
    return r;
}
static __device__ __forceinline__ void mma_tf32(float d[4],
                                                unsigned a0, unsigned a1,
                                                unsigned a2, unsigned a3,
                                                unsigned b0, unsigned b1) {
    asm volatile(
        "mma.sync.aligned.m16n8k8.row.col.f32.tf32.tf32.f32 "
        "{%0,%1,%2,%3}, {%4,%5,%6,%7}, {%8,%9}, {%0,%1,%2,%3};"
        : "+f"(d[0]), "+f"(d[1]), "+f"(d[2]), "+f"(d[3])
        : "r"(a0), "r"(a1), "r"(a2), "r"(a3), "r"(b0), "r"(b1));
}

// ---------------------------------------------------------------------------
// adj precompute (unchanged)
// ---------------------------------------------------------------------------
__global__ void adj_kernel(const int* __restrict__ qt,
                           const float* __restrict__ one_hot,
                           const float* __restrict__ graphs)
{
    __shared__ int nzIdx[1024];
    __shared__ int nzCnt;
    const int k = blockIdx.x;
    const int tid = threadIdx.x;
    if (tid == 0) nzCnt = 0;
    __syncthreads();
    const int q0 = __ldg(&qt[0]);
    const float v = __ldg(&one_hot[(size_t)q0 * 1024 + tid]);
    if (v > 0.5f) { int p = atomicAdd(&nzCnt, 1); nzIdx[p] = tid; }
    __syncthreads();
    const int cnt = nzCnt;
    const float denom = fmaxf((float)cnt, 1.0f);
    float s = 0.0f;
    for (int t = 0; t < cnt; ++t)
        s += __ldg(&graphs[((size_t)k * 1024 + (size_t)nzIdx[t]) * 1024 + tid]);
    g_adj[k * 1024 + tid] = clipf(s / denom, -5.0f, 5.0f);
}

// ---------------------------------------------------------------------------
// P1[k][c][j] = bn1[k][j] + sum_e clip(kcE[c][e],±5) * Wn1[k][192+e][j]
// (kc half of neighbor layer-1, batch-independent). grid=(1024,2), block=64.
// ---------------------------------------------------------------------------
__global__ void p1_kernel(const float* __restrict__ kcE,
                          const float* __restrict__ Wn1,
                          const float* __restrict__ bn1)
{
    __shared__ float kcS[64];
    const int c = blockIdx.x, k = blockIdx.y, j = threadIdx.x;
    kcS[j] = clipf(__ldg(&kcE[c * 64 + j]), -5.0f, 5.0f);
    __syncthreads();
    float s = __ldg(&bn1[k * 64 + j]);
#pragma unroll 4
    for (int e = 0; e < 64; ++e)
        s = fmaf(kcS[e], __ldg(&Wn1[(size_t)k * 16384 + (size_t)(192 + e) * 64 + j]), s);
    g_P1[((size_t)k * 1024 + c) * 64 + j] = s;
}

// ---------------------------------------------------------------------------
// Stage a 64x64 weight block (row pitch `pitch`) into fragment order, tf32.
// Frag slot for (k,j): kc=k/8, h=(k%8)/4, t=k%4, nc=j/8, g=j%8:
//   Wf[(kc*8+nc)*64 + (g*4+t)*2 + h]
// so warp-lane LDS.64 at (kc*8+nc)*64 + lane*2 yields {b0,b1}.
// ---------------------------------------------------------------------------
static __device__ __forceinline__ void stage_frag(const float* __restrict__ g,
                                                  int pitch, float* __restrict__ Wf,
                                                  int tid)
{
    for (int i = tid; i < 4096; i += NT) {
        const int k = i >> 6, j = i & 63;
        const float w = __ldg(&g[k * pitch + j]);
        const int kc = k >> 3, kk = k & 7;
        const int h = kk >> 2, t = kk & 3;
        const int nc = j >> 3, gg = j & 7;
        Wf[(kc * 8 + nc) * 64 + (gg * 4 + t) * 2 + h] = __uint_as_float(f2tf(w));
    }
}

// ---------------------------------------------------------------------------
// K=64 GEMM tile via mma.sync tf32: warp (wm,wn) computes rows m0..m0+15,
// cols wn*32..wn*32+31. A: [k][ROWP] in shared. acc accumulates.
// ---------------------------------------------------------------------------
static __device__ __forceinline__ void gemm_mma(const float* __restrict__ A,
                                                const float* __restrict__ Wf,
                                                int m0, int wn, int lane,
                                                float acc[4][4])
{
    const int t = lane & 3, g = lane >> 2;
    const float* Ab = A + m0 + g;
#pragma unroll
    for (int kc = 0; kc < 8; ++kc) {
        const float* Ak = Ab + (kc * 8 + t) * ROWP;
        const unsigned a0 = f2tf(Ak[0]);
        const unsigned a1 = f2tf(Ak[8]);
        const unsigned a2 = f2tf(Ak[4 * ROWP]);
        const unsigned a3 = f2tf(Ak[4 * ROWP + 8]);
#pragma unroll
        for (int c4 = 0; c4 < 4; ++c4) {
            const int nc = wn * 4 + c4;
            const float2 b = *reinterpret_cast<const float2*>(
                Wf + (kc * 8 + nc) * 64 + lane * 2);
            mma_tf32(acc[c4], a0, a1, a2, a3,
                     __float_as_uint(b.x), __float_as_uint(b.y));
        }
    }
}
static __device__ __forceinline__ void zacc(float acc[4][4]) {
#pragma unroll
    for (int i = 0; i < 4; ++i)
#pragma unroll
        for (int j = 0; j < 4; ++j) acc[i][j] = 0.0f;
}

// ---------------------------------------------------------------------------
// Main fused kernel: one block per (b, 128-row c-tile). 512 threads, 16 warps.
// Warp: wm = warpId & 7 (m-tile of 16 rows), wn = warpId >> 3 (n half).
// Thread fragment rows: rA = m0 + lane/4, rB = rA + 8.
// Fragment cols per c4: j0 = (wn*4+c4)*8 + 2*(lane%4), j0+1.
// ---------------------------------------------------------------------------
extern __shared__ float dynsmem[];

__global__ void __launch_bounds__(NT, 1)
main_kernel(const int*   __restrict__ qt,
            const float* __restrict__ ht,
            const float* __restrict__ one_hot,
            const float* __restrict__ kcE,
            const float* __restrict__ nwp,
            const float* __restrict__ Ws1, const float* __restrict__ bs1,
            const float* __restrict__ Ws2, const float* __restrict__ bs2,
            const float* __restrict__ Wn1, const float* __restrict__ bn1,
            const float* __restrict__ Wn2, const float* __restrict__ bn2,
            const float* __restrict__ ea_w,
            const float* __restrict__ We,  const float* __restrict__ be,
            const float* __restrict__ Wa,  const float* __restrict__ ba,
            const float* __restrict__ W_ih, const float* __restrict__ b_ih,
            const float* __restrict__ W_hh, const float* __restrict__ b_hh,
            const float* __restrict__ Wpv, const float* __restrict__ bp,
            float* __restrict__ out)
{
    const int tid  = threadIdx.x;
    const int lane = tid & 31;
    const int warpId = tid >> 5;
    const int wm = warpId & 7;
    const int wn = warpId >> 3;
    const int m0 = wm * 16;
    const int t4 = lane & 3;
    const int g8 = lane >> 2;
    const int rA = m0 + g8;
    const int rB = rA + 8;
    const int c0 = blockIdx.x * 128;
    const int b  = blockIdx.y;

    float* pool = dynsmem;
    float* GB = pool + OFF_GB;
    float* U  = pool + OFF_U;
    float* H1 = pool + OFF_H1;   // also SIG
    float* MN = pool + OFF_MN;   // also RES
    float* HT = pool + OFF_HT;
    float* Wf = pool + OFF_WF;

    __shared__ float adj0S[128], adj1S[128], eaS[128], WpS[64];
    __shared__ float yS2[256];
    __shared__ float selfH1[16][64];
    __shared__ int selfRows[128];
    __shared__ int selfCnt;

    if (tid == 0) selfCnt = 0;
    __syncthreads();

    // ---------------- Phase A: metadata + HT / U ------------------------------
    const int qb = __ldg(&qt[b]);
    if (tid < 128) {
        const int row = tid;
        const int c = c0 + row;
        const float m = __ldg(&one_hot[(size_t)qb * 1024 + c]);
        adj0S[row] = g_adj[c];
        adj1S[row] = g_adj[1024 + c];
        eaS[row]   = __ldg(&ea_w[c]);
        if (m > 0.5f) { int p = atomicAdd(&selfCnt, 1); selfRows[p] = row; }
    }
    if (tid < 64) WpS[tid] = __ldg(&Wpv[tid]);

    for (int i = tid; i < 2048; i += NT) {
        const int row = i & 127;
        const int f4  = i >> 7;
        const float4 v = __ldg(reinterpret_cast<const float4*>(
                               &ht[((size_t)b * 1024 + c0 + row) * 64]) + f4);
        const int f = f4 * 4;
        HT[(f + 0) * ROWP + row] = v.x;
        HT[(f + 1) * ROWP + row] = v.y;
        HT[(f + 2) * ROWP + row] = v.z;
        HT[(f + 3) * ROWP + row] = v.w;
        U[(f + 0) * ROWP + row] = clipf(v.x, -5.0f, 5.0f);
        U[(f + 1) * ROWP + row] = clipf(v.y, -5.0f, 5.0f);
        U[(f + 2) * ROWP + row] = clipf(v.z, -5.0f, 5.0f);
        U[(f + 3) * ROWP + row] = clipf(v.w, -5.0f, 5.0f);
    }
    __syncthreads();

    const float w = clipf(__ldg(&nwp[0]), 0.1f, 0.9f);
    float acc[4][4];

    // ---------------- Phase B: neighbor MLPs ----------------------------------
#pragma unroll 1
    for (int k = 0; k < 2; ++k) {
        // layer 1: H1 = relu(U @ Wn1[k][128:192] + P1[k][c])
        stage_frag(Wn1 + (size_t)k * 16384 + 128 * 64, 64, Wf, tid);
        __syncthreads();
        zacc(acc);
        gemm_mma(U, Wf, m0, wn, lane, acc);
        __syncthreads();
        const float* P1k = g_P1 + (size_t)k * 1024 * 64;
#pragma unroll
        for (int c4 = 0; c4 < 4; ++c4) {
            const int j0 = (wn * 4 + c4) * 8 + 2 * t4;
            const float2 pa = *reinterpret_cast<const float2*>(&P1k[(size_t)(c0 + rA) * 64 + j0]);
            const float2 pb = *reinterpret_cast<const float2*>(&P1k[(size_t)(c0 + rB) * 64 + j0]);
            H1[j0 * ROWP + rA]       = fmaxf(acc[c4][0] + pa.x, 0.0f);
            H1[(j0 + 1) * ROWP + rA] = fmaxf(acc[c4][1] + pa.y, 0.0f);
            H1[j0 * ROWP + rB]       = fmaxf(acc[c4][2] + pb.x, 0.0f);
            H1[(j0 + 1) * ROWP + rB] = fmaxf(acc[c4][3] + pb.y, 0.0f);
        }
        __syncthreads();

        // layer 2 + combine
        stage_frag(Wn2 + (size_t)k * 4096, 64, Wf, tid);
        __syncthreads();
        zacc(acc);
        gemm_mma(H1, Wf, m0, wn, lane, acc);
        __syncthreads();
#pragma unroll
        for (int c4 = 0; c4 < 4; ++c4) {
            const int j0 = (wn * 4 + c4) * 8 + 2 * t4;
#pragma unroll
            for (int h = 0; h < 2; ++h) {
                const int j = j0 + h;
                const float bb = __ldg(&bn2[k * 64 + j]);
                const float nbA = fminf(fmaxf(acc[c4][h] + bb, 0.0f), 5.0f);
                const float nbB = fminf(fmaxf(acc[c4][2 + h] + bb, 0.0f), 5.0f);
                float* mA = &MN[j * ROWP + rA];
                float* mB = &MN[j * ROWP + rB];
                if (k == 0) {
                    *mA = clipf(adj0S[rA] * nbA, -5.0f, 5.0f);
                    *mB = clipf(adj0S[rB] * nbB, -5.0f, 5.0f);
                } else {
                    *mA = clipf(w * (*mA) + (1.0f - w) * adj1S[rA] * nbA, -5.0f, 5.0f);
                    *mB = clipf(w * (*mB) + (1.0f - w) * adj1S[rB] * nbB, -5.0f, 5.0f);
                }
            }
        }
        __syncthreads();
    }

    // ---------------- Phase C: sparse self-MLP fixup --------------------------
    {
        const int nSelf = selfCnt;
        for (int s = warpId; s < nSelf; s += 16) {
            const int row = selfRows[s];
            const int c = c0 + row;
            float a1 = __ldg(&bs1[lane]);
            float a2 = __ldg(&bs1[lane + 32]);
#pragma unroll 4
            for (int i = 0; i < 64; ++i) {
                const float xi = HT[i * ROWP + row];
                a1 = fmaf(xi, __ldg(&Ws1[i * 64 + lane]), a1);
                a2 = fmaf(xi, __ldg(&Ws1[i * 64 + lane + 32]), a2);
            }
#pragma unroll 4
            for (int i = 0; i < 64; ++i) {
                const float xi = __ldg(&kcE[(size_t)c * 64 + i]);
                a1 = fmaf(xi, __ldg(&Ws1[(64 + i) * 64 + lane]), a1);
                a2 = fmaf(xi, __ldg(&Ws1[(64 + i) * 64 + lane + 32]), a2);
            }
            selfH1[warpId][lane]      = fmaxf(a1, 0.0f);
            selfH1[warpId][lane + 32] = fmaxf(a2, 0.0f);
            __syncwarp();
            float o1 = __ldg(&bs2[lane]);
            float o2 = __ldg(&bs2[lane + 32]);
#pragma unroll 4
            for (int i = 0; i < 64; ++i) {
                const float h = selfH1[warpId][i];
                o1 = fmaf(h, __ldg(&Ws2[i * 64 + lane]), o1);
                o2 = fmaf(h, __ldg(&Ws2[i * 64 + lane + 32]), o2);
            }
            MN[lane * ROWP + row]        = fminf(fmaxf(o1, 0.0f), 10.0f);
            MN[(lane + 32) * ROWP + row] = fminf(fmaxf(o2, 0.0f), 10.0f);
            __syncwarp();
        }
    }
    __syncthreads();

    // ---------------- Phase D: edge-attention residual ------------------------
    float* SIG = H1;
    float* RES = MN;

    stage_frag(We, 64, Wf, tid);
    __syncthreads();
    zacc(acc);
    gemm_mma(MN, Wf, m0, wn, lane, acc);
    __syncthreads();
#pragma unroll
    for (int c4 = 0; c4 < 4; ++c4) {
        const int j0 = (wn * 4 + c4) * 8 + 2 * t4;
#pragma unroll
        for (int h = 0; h < 2; ++h) {
            const int j = j0 + h;
            const float bb = __ldg(&be[j]);
            SIG[j * ROWP + rA] = sigf(acc[c4][h] + bb);
            SIG[j * ROWP + rB] = sigf(acc[c4][2 + h] + bb);
        }
    }
    __syncthreads();

    stage_frag(Wa, 64, Wf, tid);
    __syncthreads();
    zacc(acc);
    gemm_mma(MN, Wf, m0, wn, lane, acc);
    __syncthreads();   // all GEMM reads of MN done before in-place RES writes
#pragma unroll
    for (int c4 = 0; c4 < 4; ++c4) {
        const int j0 = (wn * 4 + c4) * 8 + 2 * t4;
#pragma unroll
        for (int h = 0; h < 2; ++h) {
            const int j = j0 + h;
            const float bb = __ldg(&ba[j]);
            {
                const float mn = MN[j * ROWP + rA];
                const float g  = eaS[rA];
                RES[j * ROWP + rA] =
                    mn - g * SIG[j * ROWP + rA] * mn + g * tanhf(acc[c4][h] + bb);
            }
            {
                const float mn = MN[j * ROWP + rB];
                const float g  = eaS[rB];
                RES[j * ROWP + rB] =
                    mn - g * SIG[j * ROWP + rB] * mn + g * tanhf(acc[c4][2 + h] + bb);
            }
        }
    }
    __syncthreads();

    // ---------------- Phase E: GRU + readout ----------------------------------
    // gh = ht @ W_hh + b_hh (3 passes into GB)
#pragma unroll 1
    for (int p = 0; p < 3; ++p) {
        stage_frag(W_hh + p * 64, 192, Wf, tid);
        __syncthreads();
        zacc(acc);
        gemm_mma(HT, Wf, m0, wn, lane, acc);
        __syncthreads();
#pragma unroll
        for (int c4 = 0; c4 < 4; ++c4) {
            const int j0 = (wn * 4 + c4) * 8 + 2 * t4;
#pragma unroll
            for (int h = 0; h < 2; ++h) {
                const int j = p * 64 + j0 + h;
                const float bb = __ldg(&b_hh[j]);
                GB[j * ROWP + rA] = acc[c4][h] + bb;
                GB[j * ROWP + rB] = acc[c4][2 + h] + bb;
            }
        }
        __syncthreads();
    }

    // gi passes 0,1: r / z gates fused in place
#pragma unroll 1
    for (int p = 0; p < 2; ++p) {
        stage_frag(W_ih + p * 64, 192, Wf, tid);
        __syncthreads();
        zacc(acc);
        gemm_mma(RES, Wf, m0, wn, lane, acc);
        __syncthreads();
#pragma unroll
        for (int c4 = 0; c4 < 4; ++c4) {
            const int j0 = (wn * 4 + c4) * 8 + 2 * t4;
#pragma unroll
            for (int h = 0; h < 2; ++h) {
                const int j = p * 64 + j0 + h;
                const float bb = __ldg(&b_ih[j]);
                GB[j * ROWP + rA] = sigf(acc[c4][h] + bb + GB[j * ROWP + rA]);
                GB[j * ROWP + rB] = sigf(acc[c4][2 + h] + bb + GB[j * ROWP + rB]);
            }
        }
        __syncthreads();
    }

    // gi pass 2: n, h_next, y-partials
    stage_frag(W_ih + 128, 192, Wf, tid);
    __syncthreads();
    zacc(acc);
    gemm_mma(RES, Wf, m0, wn, lane, acc);
    __syncthreads();
    {
        float ypA = 0.0f, ypB = 0.0f;
#pragma unroll
        for (int c4 = 0; c4 < 4; ++c4) {
            const int j0 = (wn * 4 + c4) * 8 + 2 * t4;
#pragma unroll
            for (int h = 0; h < 2; ++h) {
                const int j = j0 + h;
                const float bb = __ldg(&b_ih[128 + j]);
                const float wp = WpS[j];
                {
                    const float r  = GB[j * ROWP + rA];
                    const float z  = GB[(64 + j) * ROWP + rA];
                    const float hn = GB[(128 + j) * ROWP + rA];
                    const float n  = tanhf(acc[c4][h] + bb + r * hn);
                    const float hv = HT[j * ROWP + rA];
                    ypA += ((1.0f - z) * n + z * hv) * wp;
                }
                {
                    const float r  = GB[j * ROWP + rB];
                    const float z  = GB[(64 + j) * ROWP + rB];
                    const float hn = GB[(128 + j) * ROWP + rB];
                    const float n  = tanhf(acc[c4][2 + h] + bb + r * hn);
                    const float hv = HT[j * ROWP + rB];
                    ypB += ((1.0f - z) * n + z * hv) * wp;
                }
            }
        }
        ypA += __shfl_xor_sync(0xffffffffu, ypA, 1);
        ypA += __shfl_xor_sync(0xffffffffu, ypA, 2);
        ypB += __shfl_xor_sync(0xffffffffu, ypB, 1);
        ypB += __shfl_xor_sync(0xffffffffu, ypB, 2);
        if (t4 == 0) {
            yS2[wn * 128 + rA] = ypA;
            yS2[wn * 128 + rB] = ypB;
        }
    }
    __syncthreads();

    if (tid < 128) {
        out[(size_t)b * 1024 + c0 + tid] =
            sigf(yS2[tid] + yS2[128 + tid] + __ldg(&bp[0]));
    }
}

// ---------------------------------------------------------------------------
// Launcher
// ---------------------------------------------------------------------------
extern "C" void kernel_launch(void* const* d_in, const int* in_sizes, int n_in,
                              void* d_out, int out_size)
{
    const int*   qt     = (const int*)  d_in[1];
    const float* ht     = (const float*)d_in[2];
    const float* oh     = (const float*)d_in[3];
    const float* kcE    = (const float*)d_in[4];
    const float* graphs = (const float*)d_in[5];
    const float* nw     = (const float*)d_in[6];
    const float* Ws1    = (const float*)d_in[7];
    const float* bs1    = (const float*)d_in[8];
    const float* Ws2    = (const float*)d_in[9];
    const float* bs2    = (const float*)d_in[10];
    const float* Wn1    = (const float*)d_in[11];
    const float* bn1    = (const float*)d_in[12];
    const float* Wn2    = (const float*)d_in[13];
    const float* bn2    = (const float*)d_in[14];
    const float* ea     = (const float*)d_in[15];
    const float* We     = (const float*)d_in[16];
    const float* be     = (const float*)d_in[17];
    const float* Wa     = (const float*)d_in[18];
    const float* ba     = (const float*)d_in[19];
    const float* Wih    = (const float*)d_in[20];
    const float* bih    = (const float*)d_in[21];
    const float* Whh    = (const float*)d_in[22];
    const float* bhh    = (const float*)d_in[23];
    const float* Wp     = (const float*)d_in[24];
    const float* bp     = (const float*)d_in[25];
    float* out = (float*)d_out;

    adj_kernel<<<2, 1024>>>(qt, oh, graphs);
    p1_kernel<<<dim3(1024, 2), 64>>>(kcE, Wn1, bn1);

    const int smemBytes = SMEM_FLOATS * (int)sizeof(float); // 181504
    cudaFuncSetAttribute(main_kernel,
                         cudaFuncAttributeMaxDynamicSharedMemorySize, smemBytes);

    dim3 grid(8, 256);
    main_kernel<<<grid, NT, smemBytes>>>(qt, ht, oh, kcE, nw,
                                         Ws1, bs1, Ws2, bs2,
                                         Wn1, bn1, Wn2, bn2,
                                         ea, We, be, Wa, ba,
                                         Wih, bih, Whh, bhh, Wp, bp, out);
}

// round 7
// speedup vs baseline: 2.2210x; 1.5407x over previous
#include <cuda_runtime.h>
#include <cstdint>

#define NT 512
#define ROWP 136
#define SEG  8704          // 64 * ROWP

// Dynamic pool offsets (floats)
#define OFF_U    0         // U (B) / GB cols 0-63 (E)
#define OFF_H1A  8704      // H1a (B) / SIG (D) / GB 64-127 (E)
#define OFF_H1B  17408     // H1b (B) / selfH1 (C) / GB 128-191 (E)
#define OFF_MN   26112     // MN (B..D) / RES (D..E, in place)
#define OFF_HT   34816     // raw ht (persistent)
#define OFF_WF0  43520     // weight staging buffer 0 (4096)
#define OFF_WF1  47616     // weight staging buffer 1 (4096)
#define SMEM_FLOATS 51712  // 206848 bytes dynamic

__device__ float g_adj[2048];
__device__ float g_P1[2 * 1024 * 64];

static __device__ __forceinline__ float clipf(float x, float lo, float hi) {
    return fminf(fmaxf(x, lo), hi);
}
static __device__ __forceinline__ float sigf(float x) {
    return 1.0f / (1.0f + expf(-x));
}
static __device__ __forceinline__ unsigned f2tf(float x) {
    unsigned r;
    asm("cvt.rna.tf32.f32 %0, %1;" : "=r"(r) : "f"(x));
    return r;
}
static __device__ __forceinline__ void mma_tf32(float d[4],
                                                unsigned a0, unsigned a1,
                                                unsigned a2, unsigned a3,
                                                unsigned b0, unsigned b1) {
    asm volatile(
        "mma.sync.aligned.m16n8k8.row.col.f32.tf32.tf32.f32 "
        "{%0,%1,%2,%3}, {%4,%5,%6,%7}, {%8,%9}, {%0,%1,%2,%3};"
        : "+f"(d[0]), "+f"(d[1]), "+f"(d[2]), "+f"(d[3])
        : "r"(a0), "r"(a1), "r"(a2), "r"(a3), "r"(b0), "r"(b1));
}

// ---------------------------------------------------------------------------
// adj: grid (2,8), block 128
// ---------------------------------------------------------------------------
__global__ void adj_kernel(const int* __restrict__ qt,
                           const float* __restrict__ one_hot,
                           const float* __restrict__ graphs)
{
    __shared__ int nzIdx[1024];
    __shared__ int nzCnt;
    const int k = blockIdx.x;
    const int d = blockIdx.y * 128 + threadIdx.x;
    const int tid = threadIdx.x;
    if (tid == 0) nzCnt = 0;
    __syncthreads();
    const int q0 = __ldg(&qt[0]);
    for (int c = tid; c < 1024; c += 128) {
        if (__ldg(&one_hot[(size_t)q0 * 1024 + c]) > 0.5f) {
            int p = atomicAdd(&nzCnt, 1);
            nzIdx[p] = c;
        }
    }
    __syncthreads();
    const int cnt = nzCnt;
    const float denom = fmaxf((float)cnt, 1.0f);
    float s = 0.0f;
    for (int t = 0; t < cnt; ++t)
        s += __ldg(&graphs[((size_t)k * 1024 + (size_t)nzIdx[t]) * 1024 + d]);
    g_adj[k * 1024 + d] = clipf(s / denom, -5.0f, 5.0f);
}

// ---------------------------------------------------------------------------
// P1[k][c][j] = bn1[k][j] + sum_e clip(kcE[c][e],±5) * Wn1[k][192+e][j]
// ---------------------------------------------------------------------------
__global__ void p1_kernel(const float* __restrict__ kcE,
                          const float* __restrict__ Wn1,
                          const float* __restrict__ bn1)
{
    __shared__ float kcS[64];
    const int c = blockIdx.x, k = blockIdx.y, j = threadIdx.x;
    kcS[j] = clipf(__ldg(&kcE[c * 64 + j]), -5.0f, 5.0f);
    __syncthreads();
    float s = __ldg(&bn1[k * 64 + j]);
#pragma unroll 4
    for (int e = 0; e < 64; ++e)
        s = fmaf(kcS[e], __ldg(&Wn1[(size_t)k * 16384 + (size_t)(192 + e) * 64 + j]), s);
    g_P1[((size_t)k * 1024 + c) * 64 + j] = s;
}

// ---------------------------------------------------------------------------
// Weight prefetch (regs) / store (frag order, tf32)
// ---------------------------------------------------------------------------
static __device__ __forceinline__ void wload(const float* __restrict__ g,
                                             int pitch, int tid, float pw[8])
{
#pragma unroll
    for (int q = 0; q < 8; ++q) {
        const int i = tid + q * NT;
        const int k = i >> 6, j = i & 63;
        pw[q] = __ldg(&g[k * pitch + j]);
    }
}
static __device__ __forceinline__ void wstore(const float pw[8],
                                              float* __restrict__ Wf, int tid)
{
#pragma unroll
    for (int q = 0; q < 8; ++q) {
        const int i = tid + q * NT;
        const int k = i >> 6, j = i & 63;
        const int kc = k >> 3, kk = k & 7;
        const int h = kk >> 2, t = kk & 3;
        const int nc = j >> 3, gg = j & 7;
        Wf[(kc * 8 + nc) * 64 + (gg * 4 + t) * 2 + h] = __uint_as_float(f2tf(pw[q]));
    }
}

// A fragments: 16 rows (m0..m0+15) x K=64, converted once, reused.
static __device__ __forceinline__ void load_af(const float* __restrict__ A,
                                               int m0, int t4, int g8,
                                               unsigned af[8][4])
{
    const float* Ab = A + m0 + g8;
#pragma unroll
    for (int kc = 0; kc < 8; ++kc) {
        const float* Ak = Ab + (kc * 8 + t4) * ROWP;
        af[kc][0] = f2tf(Ak[0]);
        af[kc][1] = f2tf(Ak[8]);
        af[kc][2] = f2tf(Ak[4 * ROWP]);
        af[kc][3] = f2tf(Ak[4 * ROWP + 8]);
    }
}
static __device__ __forceinline__ void gemm_frag(const unsigned af[8][4],
                                                 const float* __restrict__ Wf,
                                                 int wn, int lane, float acc[4][4])
{
#pragma unroll
    for (int kc = 0; kc < 8; ++kc) {
#pragma unroll
        for (int c4 = 0; c4 < 4; ++c4) {
            const float2 b = *reinterpret_cast<const float2*>(
                Wf + (kc * 8 + wn * 4 + c4) * 64 + lane * 2);
            mma_tf32(acc[c4], af[kc][0], af[kc][1], af[kc][2], af[kc][3],
                     __float_as_uint(b.x), __float_as_uint(b.y));
        }
    }
}
static __device__ __forceinline__ void zacc(float acc[4][4]) {
#pragma unroll
    for (int i = 0; i < 4; ++i)
#pragma unroll
        for (int j = 0; j < 4; ++j) acc[i][j] = 0.0f;
}

// ---------------------------------------------------------------------------
// Main fused kernel
// ---------------------------------------------------------------------------
extern __shared__ float dynsmem[];

__global__ void __launch_bounds__(NT, 1)
main_kernel(const int*   __restrict__ qt,
            const float* __restrict__ ht,
            const float* __restrict__ one_hot,
            const float* __restrict__ kcE,
            const float* __restrict__ nwp,
            const float* __restrict__ Ws1, const float* __restrict__ bs1,
            const float* __restrict__ Ws2, const float* __restrict__ bs2,
            const float* __restrict__ Wn1, const float* __restrict__ bn1,
            const float* __restrict__ Wn2, const float* __restrict__ bn2,
            const float* __restrict__ ea_w,
            const float* __restrict__ We,  const float* __restrict__ be,
            const float* __restrict__ Wa,  const float* __restrict__ ba,
            const float* __restrict__ W_ih, const float* __restrict__ b_ih,
            const float* __restrict__ W_hh, const float* __restrict__ b_hh,
            const float* __restrict__ Wpv, const float* __restrict__ bp,
            float* __restrict__ out)
{
    const int tid  = threadIdx.x;
    const int lane = tid & 31;
    const int warpId = tid >> 5;
    const int wm = warpId & 7;
    const int wn = warpId >> 3;
    const int m0 = wm * 16;
    const int t4 = lane & 3;
    const int g8 = lane >> 2;
    const int rA = m0 + g8;
    const int rB = rA + 8;
    const int c0 = blockIdx.x * 128;
    const int b  = blockIdx.y;

    float* pool = dynsmem;
    float* U   = pool + OFF_U;
    float* H1A = pool + OFF_H1A;   // SIG in D
    float* H1B = pool + OFF_H1B;   // selfH1 scratch in C
    float* MN  = pool + OFF_MN;    // RES in D..E
    float* HT  = pool + OFF_HT;
    float* GB  = pool + OFF_U;     // 192 x ROWP in phase E
    float* Wf0 = pool + OFF_WF0;
    float* Wf1 = pool + OFF_WF1;

    __shared__ float adj0S[128], adj1S[128], eaS[128], WpS[64];
    __shared__ float yS2[256];
    __shared__ int selfRows[128];
    __shared__ int selfCnt;

    if (tid == 0) selfCnt = 0;
    __syncthreads();

    float pw[8];
    unsigned af[8][4];
    float acc[4][4];

    // ---------------- Phase A: prefetch S0 weights + metadata + HT/U ----------
    wload(Wn1 + 128 * 64, 64, tid, pw);            // S0 = Wn1[0] rows 128..191

    const int qb = __ldg(&qt[b]);
    if (tid < 128) {
        const int row = tid;
        const int c = c0 + row;
        const float m = __ldg(&one_hot[(size_t)qb * 1024 + c]);
        adj0S[row] = g_adj[c];
        adj1S[row] = g_adj[1024 + c];
        eaS[row]   = __ldg(&ea_w[c]);
        if (m > 0.5f) { int p = atomicAdd(&selfCnt, 1); selfRows[p] = row; }
    }
    if (tid < 64) WpS[tid] = __ldg(&Wpv[tid]);

    for (int i = tid; i < 2048; i += NT) {
        const int row = i & 127;
        const int f4  = i >> 7;
        const float4 v = __ldg(reinterpret_cast<const float4*>(
                               &ht[((size_t)b * 1024 + c0 + row) * 64]) + f4);
        const int f = f4 * 4;
        HT[(f + 0) * ROWP + row] = v.x;
        HT[(f + 1) * ROWP + row] = v.y;
        HT[(f + 2) * ROWP + row] = v.z;
        HT[(f + 3) * ROWP + row] = v.w;
        U[(f + 0) * ROWP + row] = clipf(v.x, -5.0f, 5.0f);
        U[(f + 1) * ROWP + row] = clipf(v.y, -5.0f, 5.0f);
        U[(f + 2) * ROWP + row] = clipf(v.z, -5.0f, 5.0f);
        U[(f + 3) * ROWP + row] = clipf(v.w, -5.0f, 5.0f);
    }
    wstore(pw, Wf0, tid);
    __syncthreads();

    const float w = clipf(__ldg(&nwp[0]), 0.1f, 0.9f);

    // ---------------- S0: U @ Wn1[0] -> H1A -----------------------------------
    wload(Wn1 + 16384 + 128 * 64, 64, tid, pw);    // S1 = Wn1[1]
    load_af(U, m0, t4, g8, af);
    zacc(acc);
    gemm_frag(af, Wf0, wn, lane, acc);
    wstore(pw, Wf1, tid);
    {
        const float* P1k = g_P1;
#pragma unroll
        for (int c4 = 0; c4 < 4; ++c4) {
            const int j0 = (wn * 4 + c4) * 8 + 2 * t4;
            const float2 pa = *reinterpret_cast<const float2*>(&P1k[(size_t)(c0 + rA) * 64 + j0]);
            const float2 pb = *reinterpret_cast<const float2*>(&P1k[(size_t)(c0 + rB) * 64 + j0]);
            H1A[j0 * ROWP + rA]       = fmaxf(acc[c4][0] + pa.x, 0.0f);
            H1A[(j0 + 1) * ROWP + rA] = fmaxf(acc[c4][1] + pa.y, 0.0f);
            H1A[j0 * ROWP + rB]       = fmaxf(acc[c4][2] + pb.x, 0.0f);
            H1A[(j0 + 1) * ROWP + rB] = fmaxf(acc[c4][3] + pb.y, 0.0f);
        }
    }
    __syncthreads();

    // ---------------- S1: U @ Wn1[1] -> H1B (af reuse) ------------------------
    wload(Wn2, 64, tid, pw);                       // S2 = Wn2[0]
    zacc(acc);
    gemm_frag(af, Wf1, wn, lane, acc);
    wstore(pw, Wf0, tid);
    {
        const float* P1k = g_P1 + (size_t)1024 * 64;
#pragma unroll
        for (int c4 = 0; c4 < 4; ++c4) {
            const int j0 = (wn * 4 + c4) * 8 + 2 * t4;
            const float2 pa = *reinterpret_cast<const float2*>(&P1k[(size_t)(c0 + rA) * 64 + j0]);
            const float2 pb = *reinterpret_cast<const float2*>(&P1k[(size_t)(c0 + rB) * 64 + j0]);
            H1B[j0 * ROWP + rA]       = fmaxf(acc[c4][0] + pa.x, 0.0f);
            H1B[(j0 + 1) * ROWP + rA] = fmaxf(acc[c4][1] + pa.y, 0.0f);
            H1B[j0 * ROWP + rB]       = fmaxf(acc[c4][2] + pb.x, 0.0f);
            H1B[(j0 + 1) * ROWP + rB] = fmaxf(acc[c4][3] + pb.y, 0.0f);
        }
    }
    __syncthreads();

    // ---------------- S2: H1A @ Wn2[0] -> MN (k=0) ----------------------------
    wload(Wn2 + 4096, 64, tid, pw);                // S3 = Wn2[1]
    load_af(H1A, m0, t4, g8, af);
    zacc(acc);
    gemm_frag(af, Wf0, wn, lane, acc);
    wstore(pw, Wf1, tid);
#pragma unroll
    for (int c4 = 0; c4 < 4; ++c4) {
        const int j0 = (wn * 4 + c4) * 8 + 2 * t4;
#pragma unroll
        for (int h = 0; h < 2; ++h) {
            const int j = j0 + h;
            const float bb = __ldg(&bn2[j]);
            const float nbA = fminf(fmaxf(acc[c4][h] + bb, 0.0f), 5.0f);
            const float nbB = fminf(fmaxf(acc[c4][2 + h] + bb, 0.0f), 5.0f);
            MN[j * ROWP + rA] = clipf(adj0S[rA] * nbA, -5.0f, 5.0f);
            MN[j * ROWP + rB] = clipf(adj0S[rB] * nbB, -5.0f, 5.0f);
        }
    }
    __syncthreads();

    // ---------------- S3: H1B @ Wn2[1] -> MN combine --------------------------
    wload(We, 64, tid, pw);                        // S4 = We
    load_af(H1B, m0, t4, g8, af);
    zacc(acc);
    gemm_frag(af, Wf1, wn, lane, acc);
    wstore(pw, Wf0, tid);
#pragma unroll
    for (int c4 = 0; c4 < 4; ++c4) {
        const int j0 = (wn * 4 + c4) * 8 + 2 * t4;
#pragma unroll
        for (int h = 0; h < 2; ++h) {
            const int j = j0 + h;
            const float bb = __ldg(&bn2[64 + j]);
            const float nbA = fminf(fmaxf(acc[c4][h] + bb, 0.0f), 5.0f);
            const float nbB = fminf(fmaxf(acc[c4][2 + h] + bb, 0.0f), 5.0f);
            float* mA = &MN[j * ROWP + rA];
            float* mB = &MN[j * ROWP + rB];
            *mA = clipf(w * (*mA) + (1.0f - w) * adj1S[rA] * nbA, -5.0f, 5.0f);
            *mB = clipf(w * (*mB) + (1.0f - w) * adj1S[rB] * nbB, -5.0f, 5.0f);
        }
    }
    __syncthreads();

    // ---------------- Phase C: sparse self-MLP fixup --------------------------
    {
        float* selfH1 = H1B;   // scratch, 64 floats per warp
        const int nSelf = selfCnt;
        for (int s = warpId; s < nSelf; s += 16) {
            const int row = selfRows[s];
            const int c = c0 + row;
            float a1 = __ldg(&bs1[lane]);
            float a2 = __ldg(&bs1[lane + 32]);
#pragma unroll 4
            for (int i = 0; i < 64; ++i) {
                const float xi = HT[i * ROWP + row];
                a1 = fmaf(xi, __ldg(&Ws1[i * 64 + lane]), a1);
                a2 = fmaf(xi, __ldg(&Ws1[i * 64 + lane + 32]), a2);
            }
#pragma unroll 4
            for (int i = 0; i < 64; ++i) {
                const float xi = __ldg(&kcE[(size_t)c * 64 + i]);
                a1 = fmaf(xi, __ldg(&Ws1[(64 + i) * 64 + lane]), a1);
                a2 = fmaf(xi, __ldg(&Ws1[(64 + i) * 64 + lane + 32]), a2);
            }
            selfH1[warpId * 64 + lane]      = fmaxf(a1, 0.0f);
            selfH1[warpId * 64 + lane + 32] = fmaxf(a2, 0.0f);
            __syncwarp();
            float o1 = __ldg(&bs2[lane]);
            float o2 = __ldg(&bs2[lane + 32]);
#pragma unroll 4
            for (int i = 0; i < 64; ++i) {
                const float h = selfH1[warpId * 64 + i];
                o1 = fmaf(h, __ldg(&Ws2[i * 64 + lane]), o1);
                o2 = fmaf(h, __ldg(&Ws2[i * 64 + lane + 32]), o2);
            }
            MN[lane * ROWP + row]        = fminf(fmaxf(o1, 0.0f), 10.0f);
            MN[(lane + 32) * ROWP + row] = fminf(fmaxf(o2, 0.0f), 10.0f);
            __syncwarp();
        }
    }
    __syncthreads();

    // ---------------- S4: MN @ We -> SIG --------------------------------------
    float* SIG = H1A;
    float* RES = MN;

    wload(Wa, 64, tid, pw);                        // S5 = Wa
    load_af(MN, m0, t4, g8, af);
    zacc(acc);
    gemm_frag(af, Wf0, wn, lane, acc);
    wstore(pw, Wf1, tid);
#pragma unroll
    for (int c4 = 0; c4 < 4; ++c4) {
        const int j0 = (wn * 4 + c4) * 8 + 2 * t4;
#pragma unroll
        for (int h = 0; h < 2; ++h) {
            const int j = j0 + h;
            const float bb = __ldg(&be[j]);
            SIG[j * ROWP + rA] = sigf(acc[c4][h] + bb);
            SIG[j * ROWP + rB] = sigf(acc[c4][2 + h] + bb);
        }
    }
    __syncthreads();

    // ---------------- S5: MN @ Wa -> RES (in place, af reuse) -----------------
    wload(W_hh, 192, tid, pw);                     // S6 = W_hh p0
    zacc(acc);
    gemm_frag(af, Wf1, wn, lane, acc);
    wstore(pw, Wf0, tid);
#pragma unroll
    for (int c4 = 0; c4 < 4; ++c4) {
        const int j0 = (wn * 4 + c4) * 8 + 2 * t4;
#pragma unroll
        for (int h = 0; h < 2; ++h) {
            const int j = j0 + h;
            const float bb = __ldg(&ba[j]);
            {
                const float mn = MN[j * ROWP + rA];
                const float g  = eaS[rA];
                RES[j * ROWP + rA] = mn - g * SIG[j * ROWP + rA] * mn + g * tanhf(acc[c4][h] + bb);
            }
            {
                const float mn = MN[j * ROWP + rB];
                const float g  = eaS[rB];
                RES[j * ROWP + rB] = mn - g * SIG[j * ROWP + rB] * mn + g * tanhf(acc[c4][2 + h] + bb);
            }
        }
    }
    __syncthreads();

    // ---------------- S6..S8: HT @ W_hh -> GB (af loaded once) ----------------
    load_af(HT, m0, t4, g8, af);
#pragma unroll 1
    for (int p = 0; p < 3; ++p) {
        // prefetch next stage weights
        if (p == 0)      wload(W_hh + 64, 192, tid, pw);   // S7
        else if (p == 1) wload(W_hh + 128, 192, tid, pw);  // S8
        else             wload(W_ih, 192, tid, pw);        // S9
        zacc(acc);
        gemm_frag(af, (p & 1) ? Wf1 : Wf0, wn, lane, acc);
        wstore(pw, (p & 1) ? Wf0 : Wf1, tid);
#pragma unroll
        for (int c4 = 0; c4 < 4; ++c4) {
            const int j0 = (wn * 4 + c4) * 8 + 2 * t4;
#pragma unroll
            for (int h = 0; h < 2; ++h) {
                const int j = p * 64 + j0 + h;
                const float bb = __ldg(&b_hh[j]);
                GB[j * ROWP + rA] = acc[c4][h] + bb;
                GB[j * ROWP + rB] = acc[c4][2 + h] + bb;
            }
        }
        __syncthreads();
    }

    // ---------------- S9..S10: RES @ W_ih -> gates (af loaded once) -----------
    load_af(RES, m0, t4, g8, af);
#pragma unroll 1
    for (int p = 0; p < 2; ++p) {
        if (p == 0) wload(W_ih + 64, 192, tid, pw);        // S10
        else        wload(W_ih + 128, 192, tid, pw);       // S11
        zacc(acc);
        gemm_frag(af, (p & 1) ? Wf0 : Wf1, wn, lane, acc); // S9 uses Wf1, S10 Wf0
        wstore(pw, (p & 1) ? Wf1 : Wf0, tid);
#pragma unroll
        for (int c4 = 0; c4 < 4; ++c4) {
            const int j0 = (wn * 4 + c4) * 8 + 2 * t4;
#pragma unroll
            for (int h = 0; h < 2; ++h) {
                const int j = p * 64 + j0 + h;
                const float bb = __ldg(&b_ih[j]);
                GB[j * ROWP + rA] = sigf(acc[c4][h] + bb + GB[j * ROWP + rA]);
                GB[j * ROWP + rB] = sigf(acc[c4][2 + h] + bb + GB[j * ROWP + rB]);
            }
        }
        __syncthreads();
    }

    // ---------------- S11: final gi pass + GRU + readout ----------------------
    zacc(acc);
    gemm_frag(af, Wf1, wn, lane, acc);
    {
        float ypA = 0.0f, ypB = 0.0f;
#pragma unroll
        for (int c4 = 0; c4 < 4; ++c4) {
            const int j0 = (wn * 4 + c4) * 8 + 2 * t4;
#pragma unroll
            for (int h = 0; h < 2; ++h) {
                const int j = j0 + h;
                const float bb = __ldg(&b_ih[128 + j]);
                const float wp = WpS[j];
                {
                    const float r  = GB[j * ROWP + rA];
                    const float z  = GB[(64 + j) * ROWP + rA];
                    const float hn = GB[(128 + j) * ROWP + rA];
                    const float n  = tanhf(acc[c4][h] + bb + r * hn);
                    const float hv = HT[j * ROWP + rA];
                    ypA += ((1.0f - z) * n + z * hv) * wp;
                }
                {
                    const float r  = GB[j * ROWP + rB];
                    const float z  = GB[(64 + j) * ROWP + rB];
                    const float hn = GB[(128 + j) * ROWP + rB];
                    const float n  = tanhf(acc[c4][2 + h] + bb + r * hn);
                    const float hv = HT[j * ROWP + rB];
                    ypB += ((1.0f - z) * n + z * hv) * wp;
                }
            }
        }
        ypA += __shfl_xor_sync(0xffffffffu, ypA, 1);
        ypA += __shfl_xor_sync(0xffffffffu, ypA, 2);
        ypB += __shfl_xor_sync(0xffffffffu, ypB, 1);
        ypB += __shfl_xor_sync(0xffffffffu, ypB, 2);
        if (t4 == 0) {
            yS2[wn * 128 + rA] = ypA;
            yS2[wn * 128 + rB] = ypB;
        }
    }
    __syncthreads();

    if (tid < 128) {
        out[(size_t)b * 1024 + c0 + tid] =
            sigf(yS2[tid] + yS2[128 + tid] + __ldg(&bp[0]));
    }
}

// ---------------------------------------------------------------------------
// Launcher
// ---------------------------------------------------------------------------
extern "C" void kernel_launch(void* const* d_in, const int* in_sizes, int n_in,
                              void* d_out, int out_size)
{
    const int*   qt     = (const int*)  d_in[1];
    const float* ht     = (const float*)d_in[2];
    const float* oh     = (const float*)d_in[3];
    const float* kcE    = (const float*)d_in[4];
    const float* graphs = (const float*)d_in[5];
    const float* nw     = (const float*)d_in[6];
    const float* Ws1    = (const float*)d_in[7];
    const float* bs1    = (const float*)d_in[8];
    const float* Ws2    = (const float*)d_in[9];
    const float* bs2    = (const float*)d_in[10];
    const float* Wn1    = (const float*)d_in[11];
    const float* bn1    = (const float*)d_in[12];
    const float* Wn2    = (const float*)d_in[13];
    const float* bn2    = (const float*)d_in[14];
    const float* ea     = (const float*)d_in[15];
    const float* We     = (const float*)d_in[16];
    const float* be     = (const float*)d_in[17];
    const float* Wa     = (const float*)d_in[18];
    const float* ba     = (const float*)d_in[19];
    const float* Wih    = (const float*)d_in[20];
    const float* bih    = (const float*)d_in[21];
    const float* Whh    = (const float*)d_in[22];
    const float* bhh    = (const float*)d_in[23];
    const float* Wp     = (const float*)d_in[24];
    const float* bp     = (const float*)d_in[25];
    float* out = (float*)d_out;

    adj_kernel<<<dim3(2, 8), 128>>>(qt, oh, graphs);
    p1_kernel<<<dim3(1024, 2), 64>>>(kcE, Wn1, bn1);

    const int smemBytes = SMEM_FLOATS * (int)sizeof(float); // 206848
    cudaFuncSetAttribute(main_kernel,
                         cudaFuncAttributeMaxDynamicSharedMemorySize, smemBytes);

    dim3 grid(8, 256);
    main_kernel<<<grid, NT, smemBytes>>>(qt, ht, oh, kcE, nw,
                                         Ws1, bs1, Ws2, bs2,
                                         Wn1, bn1, Wn2, bn2,
                                         ea, We, be, Wa, ba,
                                         Wih, bih, Whh, bhh, Wp, bp, out);
}